// round 8
// baseline (speedup 1.0000x reference)
#include <cuda_runtime.h>

#define NCOLS  8192
#define NWIN   513
#define NT     256
#define KPT    32

#define TLO (-1.31f)
#define THI ( 1.31f)
#define TLA (-1.70f)
#define THA ( 1.70f)

__device__ __forceinline__ unsigned f2key(float x) {
    unsigned u = __float_as_uint(x);
    return (u & 0x80000000u) ? ~u : (u | 0x80000000u);
}
__device__ __forceinline__ float key2f(unsigned k) {
    unsigned u = (k & 0x80000000u) ? (k ^ 0x80000000u) : ~k;
    return __uint_as_float(u);
}

__device__ __forceinline__ void cas(unsigned& a, unsigned& b, bool up) {
    unsigned x = a, y = b;
    unsigned mn = min(x, y), mx = max(x, y);
    a = up ? mn : mx;
    b = up ? mx : mn;
}

__device__ __forceinline__ void sort8(unsigned v[8], bool up) {
    cas(v[0], v[4], up); cas(v[1], v[5], up); cas(v[2], v[6], up); cas(v[3], v[7], up);
    cas(v[0], v[2], up); cas(v[1], v[3], up); cas(v[4], v[6], up); cas(v[5], v[7], up);
    cas(v[0], v[1], up); cas(v[2], v[3], up); cas(v[4], v[5], up); cas(v[6], v[7], up);
}

// BRANCHLESS: keepmin varies within the warp for delta<32 (R5 regression proof).
__device__ __forceinline__ void shfl_pass(unsigned v[8], int delta, bool up, int tc) {
    bool keepmin = (up == ((tc & delta) == 0));
    #pragma unroll
    for (int e = 0; e < 8; ++e) {
        unsigned o  = __shfl_xor_sync(0xffffffffu, v[e], delta);
        unsigned mn = min(v[e], o), mx = max(v[e], o);
        v[e] = keepmin ? mn : mx;
    }
}

// delta == 32 only: keepmin warp-uniform (tc&32 fixed per warp), branch is free.
__device__ __forceinline__ void smem_pass(unsigned v[8], int delta, bool up,
                                          int t, int tc, unsigned* scratch) {
    __syncthreads();
    #pragma unroll
    for (int e = 0; e < 8; ++e) scratch[t * 8 + e] = v[e];
    __syncthreads();
    bool keepmin = (up == ((tc & delta) == 0));
    int pt = t ^ delta;
    if (keepmin) {
        #pragma unroll
        for (int e = 0; e < 8; ++e) v[e] = min(v[e], scratch[pt * 8 + e]);
    } else {
        #pragma unroll
        for (int e = 0; e < 8; ++e) v[e] = max(v[e], scratch[pt * 8 + e]);
    }
}

// ---- exact fallback helpers (f2key domain; block-uniform; cold) ----
__device__ unsigned block_count(const float4* x4, unsigned K, bool ge,
                                unsigned* s_red, int tid) {
    if (tid == 0) *s_red = 0;
    __syncthreads();
    unsigned c = 0;
    for (int i = tid; i < NCOLS / 4; i += NT) {
        float4 w = x4[i];
        unsigned k0 = f2key(w.x), k1 = f2key(w.y), k2 = f2key(w.z), k3 = f2key(w.w);
        if (ge) c += (k0 >= K) + (k1 >= K) + (k2 >= K) + (k3 >= K);
        else    c += (k0 <= K) + (k1 <= K) + (k2 <= K) + (k3 <= K);
    }
    #pragma unroll
    for (int off = 16; off; off >>= 1) c += __shfl_down_sync(0xffffffffu, c, off);
    if ((tid & 31) == 0) atomicAdd(s_red, c);
    __syncthreads();
    unsigned r = *s_red;
    __syncthreads();
    return r;
}

__device__ unsigned gather_side(const float4* x4, unsigned T, int side,
                                unsigned* seg, unsigned* s_c, int tid) {
    if (tid == 0) *s_c = 0;
    __syncthreads();
    const int lane = tid & 31;
    for (int i = tid; i < NCOLS / 4; i += NT) {
        float4 w = x4[i];
        unsigned kk[4] = { f2key(w.x), f2key(w.y), f2key(w.z), f2key(w.w) };
        #pragma unroll
        for (int q = 0; q < 4; ++q) {
            bool take = side ? (kk[q] > T) : (kk[q] < T);
            unsigned m = __ballot_sync(0xffffffffu, take);
            unsigned base = 0;
            if (lane == 0 && m) base = atomicAdd(s_c, (unsigned)__popc(m));
            base = __shfl_sync(0xffffffffu, base, 0);
            if (take) {
                unsigned p = base + __popc(m & ((1u << lane) - 1u));
                if (p < 512) seg[p] = kk[q];
            }
        }
    }
    __syncthreads();
    unsigned r = *s_c;
    __syncthreads();
    return r;
}

__global__ __launch_bounds__(NT, 6)
void recall_window_kernel(const float* __restrict__ x,
                          float* __restrict__ out, int rows)
{
    __shared__ unsigned scratch[2048];   // 4 chunks of 512: Alo|Blo|Ahi|Bhi
    __shared__ unsigned wsum[16];        // two packed scans
    __shared__ unsigned s_c;
    __shared__ unsigned long long s_best;

    const int t    = threadIdx.x;
    const int lane = t & 31;
    const int wid  = t >> 5;
    const int tc   = t & 63;             // thread index within a 512-chunk
    const int row  = blockIdx.x;
    const float4* x4 = reinterpret_cast<const float4*>(x + (size_t)row * NCOLS);

    // ---- phase 1: count the 4 buckets ----
    unsigned al = 0, bl = 0, ah = 0, bh = 0;
    #pragma unroll
    for (int e4 = 0; e4 < KPT / 4; ++e4) {
        float4 w = x4[e4 * NT + t];
        float fa[4] = { w.x, w.y, w.z, w.w };
        #pragma unroll
        for (int q = 0; q < 4; ++q) {
            float f = fa[q];
            al += (f < TLA);
            bl += (f >= TLA) && (f < TLO);
            ah += (f > THA);
            bh += (f <= THA) && (f > THI);
        }
    }

    // ---- phase 2: two packed-16 block exclusive scans ----
    unsigned pa = al | (ah << 16);
    unsigned pb = bl | (bh << 16);
    unsigned ia = pa, ib = pb;
    #pragma unroll
    for (int off = 1; off < 32; off <<= 1) {
        unsigned va = __shfl_up_sync(0xffffffffu, ia, off);
        unsigned vb = __shfl_up_sync(0xffffffffu, ib, off);
        if (lane >= off) { ia += va; ib += vb; }
    }
    if (lane == 31) { wsum[wid] = ia; wsum[8 + wid] = ib; }
    __syncthreads();
    unsigned basea = 0, baseb = 0, tota = 0, totb = 0;
    #pragma unroll
    for (int w = 0; w < 8; ++w) {
        unsigned sa = wsum[w], sb = wsum[8 + w];
        if (w < wid) { basea += sa; baseb += sb; }
        tota += sa; totb += sb;
    }
    unsigned eAl = (basea + ia - pa) & 0xFFFFu, eAh = (basea + ia - pa) >> 16;
    unsigned eBl = (baseb + ib - pb) & 0xFFFFu, eBh = (baseb + ib - pb) >> 16;
    unsigned cAl = tota & 0xFFFFu, cAh = tota >> 16;
    unsigned cBl = totb & 0xFFFFu, cBh = totb >> 16;

    const bool ok_lo = (cAl <= 512u) && (cBl <= 512u) && (cAl + cBl >= 513u);
    const bool ok_hi = (cAh <= 512u) && (cBh <= 512u) && (cAh + cBh >= 513u);

    // ---- phase 3: direct scatter into 4 chunks (fast sides) ----
    {
        unsigned pAl = eAl, pBl = 512 + eBl, pAh = 1024 + eAh, pBh = 1536 + eBh;
        #pragma unroll
        for (int e4 = 0; e4 < KPT / 4; ++e4) {
            float4 w = x4[e4 * NT + t];
            float fa[4] = { w.x, w.y, w.z, w.w };
            #pragma unroll
            for (int q = 0; q < 4; ++q) {
                float f = fa[q];
                if (ok_lo && f < TLO) {
                    unsigned k = ~__float_as_uint(f);
                    if (f < TLA) scratch[pAl++] = k;
                    else         scratch[pBl++] = k;
                } else if (ok_hi && f > THI) {
                    unsigned k = __float_as_uint(f);
                    if (f > THA) scratch[pAh++] = k;
                    else         scratch[pBh++] = k;
                }
            }
        }
    }
    // fast-path pads (disjoint from scatter writes)
    if (ok_lo) {
        for (int i = (int)cAl + t; i < 512;  i += NT) scratch[i]        = 0xFFFFFFFFu;
        for (int i = (int)cBl + t; i < 512;  i += NT) scratch[512 + i]  = 0xFFFFFFFFu;
    }
    if (ok_hi) {
        for (int i = (int)cAh + t; i < 512;  i += NT) scratch[1024 + i] = 0u;
        for (int i = (int)cBh + t; i < 512;  i += NT) scratch[1536 + i] = 0u;
    }
    __syncthreads();

    // ---- exact fallbacks (cold, block-uniform, f2key domain) ----
    unsigned cAl_eff = cAl, cAh_eff = cAh;
    if (!ok_lo) {
        unsigned Kcut;
        if (block_count(x4, 0u, false, &s_c, t) >= 513u) {
            Kcut = 0u;
        } else {
            unsigned X = 0;
            for (int b = 31; b >= 0; --b) {
                unsigned X2 = X | (1u << b);
                if (block_count(x4, X2, false, &s_c, t) < 513u) X = X2;
            }
            Kcut = X + 1u;                         // exact s[512] key
        }
        unsigned c = gather_side(x4, Kcut, 0, scratch, &s_c, t);
        for (int i = (int)c + t; i < 512; i += NT) scratch[i]       = Kcut;
        for (int i = t;          i < 512; i += NT) scratch[512 + i] = Kcut;
        cAl_eff = 512u;
    }
    if (!ok_hi) {
        unsigned Y = 0;
        for (int b = 31; b >= 0; --b) {
            unsigned Y2 = Y | (1u << b);
            if (block_count(x4, Y2, true, &s_c, t) >= 513u) Y = Y2;   // exact s[7679]
        }
        unsigned c = gather_side(x4, Y, 1, scratch + 1024, &s_c, t);
        for (int i = (int)c + t; i < 512; i += NT) scratch[1024 + i] = 0u;
        for (int i = t;          i < 512; i += NT) scratch[1536 + i] = Y;
        cAh_eff = min(c, 512u);
    }
    if (t == 0) s_best = ~0ull;
    __syncthreads();

    // ---- phase 4: four independent 512-element bitonic sorts (64 thr each) ----
    unsigned v[8];
    #pragma unroll
    for (int e = 0; e < 8; ++e) v[e] = scratch[t * 8 + e];

    cas(v[0], v[1], true);  cas(v[2], v[3], false);
    cas(v[4], v[5], true);  cas(v[6], v[7], false);
    cas(v[0], v[2], true);  cas(v[1], v[3], true);
    cas(v[4], v[6], false); cas(v[5], v[7], false);
    cas(v[0], v[1], true);  cas(v[2], v[3], true);
    cas(v[4], v[5], false); cas(v[6], v[7], false);
    sort8(v, (tc & 1) == 0);

    #pragma unroll
    for (int kk = 16; kk <= 512; kk <<= 1) {
        bool up = ((tc & (kk >> 3)) == 0);
        #pragma unroll
        for (int j = kk >> 1; j >= 8; j >>= 1) {
            int delta = j >> 3;
            if (delta >= 32) smem_pass(v, delta, up, t, tc, scratch);
            else             shfl_pass(v, delta, up, tc);
        }
        sort8(v, up);
    }

    __syncthreads();
    #pragma unroll
    for (int e = 0; e < 8; ++e) scratch[t * 8 + e] = v[e];
    __syncthreads();

    // ---- phase 5: lengths + first-index argmin ----
    // bot(i) = i < cAl_eff ? Alo[i] : Blo[i - cAl_eff]
    // top(j): m = 513 - cAh_eff;  j < m ? Bhi[512 - m + j] : Ahi[j - 1]
    const unsigned m = 513u - cAh_eff;
    unsigned long long best = ~0ull;
    for (int i = t; i < NWIN; i += NT) {
        unsigned kl = ((unsigned)i < cAl_eff) ? scratch[i]
                                              : scratch[512 + i - (int)cAl_eff];
        unsigned kh = ((unsigned)i < m) ? scratch[1536 + 512 - (int)m + i]
                                        : scratch[1024 + i - 1];
        float fl = ok_lo ? __uint_as_float(~kl) : key2f(kl);
        float fh = ok_hi ? __uint_as_float(kh)  : key2f(kh);
        float len = fh - fl;
        unsigned long long p =
            ((unsigned long long)__float_as_uint(len) << 32) | (unsigned)i;
        if (p < best) best = p;
    }
    #pragma unroll
    for (int off = 16; off; off >>= 1) {
        unsigned long long o = __shfl_down_sync(0xffffffffu, best, off);
        if (o < best) best = o;
    }
    if (lane == 0) atomicMin(&s_best, best);
    __syncthreads();

    if (t == 0) {
        int idx = (int)(unsigned)(s_best & 0xffffffffu);
        unsigned kl = ((unsigned)idx < cAl_eff) ? scratch[idx]
                                                : scratch[512 + idx - (int)cAl_eff];
        unsigned kh = ((unsigned)idx < m) ? scratch[1536 + 512 - (int)m + idx]
                                          : scratch[1024 + idx - 1];
        out[row]        = ok_lo ? __uint_as_float(~kl) : key2f(kl);
        out[rows + row] = ok_hi ? __uint_as_float(kh)  : key2f(kh);
    }
}

extern "C" void kernel_launch(void* const* d_in, const int* in_sizes, int n_in,
                              void* d_out, int out_size) {
    const float* x = (const float*)d_in[0];
    float* out = (float*)d_out;
    int rows = in_sizes[0] / NCOLS;   // 4096
    recall_window_kernel<<<rows, NT>>>(x, out, rows);
}

// round 9
// speedup vs baseline: 1.1881x; 1.1881x over previous
#include <cuda_runtime.h>

#define NCOLS  8192
#define NWIN   513
#define NT     256
#define KPT    32

#define TLO (-1.31f)
#define THI ( 1.31f)
#define FINF  __int_as_float(0x7f800000)
#define FNINF __int_as_float(0xff800000)

__device__ __forceinline__ unsigned f2key(float x) {
    unsigned u = __float_as_uint(x);
    return (u & 0x80000000u) ? ~u : (u | 0x80000000u);
}
__device__ __forceinline__ float key2f(unsigned k) {
    unsigned u = (k & 0x80000000u) ? (k ^ 0x80000000u) : ~k;
    return __uint_as_float(u);
}

__device__ __forceinline__ void casf(float& a, float& b, bool up) {
    float x = a, y = b;
    float mn = fminf(x, y), mx = fmaxf(x, y);
    a = up ? mn : mx;
    b = up ? mx : mn;
}

__device__ __forceinline__ void sort8f(float v[8], bool up) {
    casf(v[0], v[4], up); casf(v[1], v[5], up); casf(v[2], v[6], up); casf(v[3], v[7], up);
    casf(v[0], v[2], up); casf(v[1], v[3], up); casf(v[4], v[6], up); casf(v[5], v[7], up);
    casf(v[0], v[1], up); casf(v[2], v[3], up); casf(v[4], v[5], up); casf(v[6], v[7], up);
}

// BRANCHLESS: keepmin varies within the warp for delta<32 (R5 regression proof).
__device__ __forceinline__ void shfl_pass(float v[8], int delta, bool up, int ts) {
    bool keepmin = (up == ((ts & delta) == 0));
    #pragma unroll
    for (int e = 0; e < 8; ++e) {
        float o  = __shfl_xor_sync(0xffffffffu, v[e], delta);
        float mn = fminf(v[e], o), mx = fmaxf(v[e], o);
        v[e] = keepmin ? mn : mx;
    }
}

// delta >= 32: keepmin warp-uniform, branch free; pure FMNMX on the fma pipe.
__device__ __forceinline__ void smem_pass(float v[8], int delta, bool up,
                                          int t, int ts, float* scratch) {
    __syncthreads();
    #pragma unroll
    for (int e = 0; e < 8; ++e) scratch[t * 8 + e] = v[e];
    __syncthreads();
    bool keepmin = (up == ((ts & delta) == 0));
    int pt = t ^ delta;
    if (keepmin) {
        #pragma unroll
        for (int e = 0; e < 8; ++e) v[e] = fminf(v[e], scratch[pt * 8 + e]);
    } else {
        #pragma unroll
        for (int e = 0; e < 8; ++e) v[e] = fmaxf(v[e], scratch[pt * 8 + e]);
    }
}

// ---- exact fallback helpers (f2key domain; block-uniform; cold) ----
__device__ unsigned block_count(const float4* x4, unsigned K, bool ge,
                                unsigned* s_red, int tid) {
    if (tid == 0) *s_red = 0;
    __syncthreads();
    unsigned c = 0;
    for (int i = tid; i < NCOLS / 4; i += NT) {
        float4 w = x4[i];
        unsigned k0 = f2key(w.x), k1 = f2key(w.y), k2 = f2key(w.z), k3 = f2key(w.w);
        if (ge) c += (k0 >= K) + (k1 >= K) + (k2 >= K) + (k3 >= K);
        else    c += (k0 <= K) + (k1 <= K) + (k2 <= K) + (k3 <= K);
    }
    #pragma unroll
    for (int off = 16; off; off >>= 1) c += __shfl_down_sync(0xffffffffu, c, off);
    if ((tid & 31) == 0) atomicAdd(s_red, c);
    __syncthreads();
    unsigned r = *s_red;
    __syncthreads();
    return r;
}

// gathers as FLOATS (key2f applied); side 0: key<T, side 1: key>T
__device__ unsigned gather_side(const float4* x4, unsigned T, int side,
                                float* seg, unsigned* s_c, int tid) {
    if (tid == 0) *s_c = 0;
    __syncthreads();
    const int lane = tid & 31;
    for (int i = tid; i < NCOLS / 4; i += NT) {
        float4 w = x4[i];
        unsigned kk[4] = { f2key(w.x), f2key(w.y), f2key(w.z), f2key(w.w) };
        #pragma unroll
        for (int q = 0; q < 4; ++q) {
            bool take = side ? (kk[q] > T) : (kk[q] < T);
            unsigned m = __ballot_sync(0xffffffffu, take);
            unsigned base = 0;
            if (lane == 0 && m) base = atomicAdd(s_c, (unsigned)__popc(m));
            base = __shfl_sync(0xffffffffu, base, 0);
            if (take) {
                unsigned p = base + __popc(m & ((1u << lane) - 1u));
                if (p < 1024) seg[p] = key2f(kk[q]);
            }
        }
    }
    __syncthreads();
    unsigned r = *s_c;
    __syncthreads();
    return r;
}

__global__ __launch_bounds__(NT, 6)
void recall_window_kernel(const float* __restrict__ x,
                          float* __restrict__ out, int rows)
{
    __shared__ float    scratch[2048];     // two 1024-float sort segments
    __shared__ unsigned wsum[8];
    __shared__ unsigned s_c;
    __shared__ unsigned long long s_best;

    const int t    = threadIdx.x;
    const int lane = t & 31;
    const int wid  = t >> 5;
    const int ts   = t & 127;
    const int row  = blockIdx.x;
    const float4* x4 = reinterpret_cast<const float4*>(x + (size_t)row * NCOLS);

    // ---- phase 1: load + count tail takes ----
    unsigned clo = 0, chi = 0;
    #pragma unroll
    for (int e4 = 0; e4 < KPT / 4; ++e4) {
        float4 w = x4[e4 * NT + t];
        clo += (w.x < TLO) + (w.y < TLO) + (w.z < TLO) + (w.w < TLO);
        chi += (w.x > THI) + (w.y > THI) + (w.z > THI) + (w.w > THI);
    }

    // ---- phase 2: block exclusive scan of packed (clo | chi<<16) ----
    unsigned packed = clo | (chi << 16);
    unsigned incl = packed;
    #pragma unroll
    for (int off = 1; off < 32; off <<= 1) {
        unsigned v = __shfl_up_sync(0xffffffffu, incl, off);
        if (lane >= off) incl += v;
    }
    if (lane == 31) wsum[wid] = incl;
    __syncthreads();
    unsigned wbase = 0, tot = 0;
    #pragma unroll
    for (int w = 0; w < 8; ++w) {
        unsigned s = wsum[w];
        if (w < wid) wbase += s;
        tot += s;
    }
    unsigned excl   = wbase + incl - packed;
    unsigned baselo = excl & 0xFFFFu, basehi = excl >> 16;
    unsigned totlo  = tot  & 0xFFFFu, tothi  = tot  >> 16;

    const bool ok_lo = (totlo >= 513u && totlo <= 1024u);
    const bool ok_hi = (tothi >= 513u && tothi <= 1024u);

    // ---- phase 3: re-read row (cache-hot), scatter floats directly ----
    if (ok_lo && ok_hi) {
        unsigned plo = baselo, phi = basehi;
        #pragma unroll
        for (int e4 = 0; e4 < KPT / 4; ++e4) {
            float4 w = x4[e4 * NT + t];
            float fa[4] = { w.x, w.y, w.z, w.w };
            #pragma unroll
            for (int q = 0; q < 4; ++q) {
                float f = fa[q];
                if (f < TLO)      scratch[plo++] = f;
                else if (f > THI) scratch[1024 + phi++] = f;
            }
        }
    }
    __syncthreads();

    unsigned c0 = totlo, c1 = tothi;
    if (!ok_lo) {                                   // exact fallback (cold)
        unsigned Kcut;
        if (block_count(x4, 0u, false, &s_c, t) >= 513u) {
            Kcut = 0u;
        } else {
            unsigned X = 0;
            for (int b = 31; b >= 0; --b) {
                unsigned X2 = X | (1u << b);
                if (block_count(x4, X2, false, &s_c, t) < 513u) X = X2;
            }
            Kcut = X + 1u;                          // exact s[512] key
        }
        c0 = gather_side(x4, Kcut, 0, scratch, &s_c, t);
        float fK = key2f(Kcut);
        for (int i = (int)c0 + t; i < 513; i += NT) scratch[i] = fK;
        c0 = 513u;
    }
    if (!ok_hi) {
        unsigned Y = 0;
        for (int b = 31; b >= 0; --b) {
            unsigned Y2 = Y | (1u << b);
            if (block_count(x4, Y2, true, &s_c, t) >= 513u) Y = Y2;   // exact s[7679]
        }
        c1 = gather_side(x4, Y, 1, scratch + 1024, &s_c, t);
        float fY = key2f(Y);
        for (int i = (int)c1 + t; i < 513; i += NT) scratch[1024 + i] = fY;
        c1 = 513u;
    }
    // pads: lo-end with +INF, hi-front with -INF
    for (int i = (int)c0 + t; i < 1024; i += NT) scratch[i]        = FINF;
    for (int i = (int)c1 + t; i < 1024; i += NT) scratch[1024 + i] = FNINF;
    if (t == 0) s_best = ~0ull;
    __syncthreads();

    // ---- phase 4: register-blocked float bitonic, two independent 1024 sorts ----
    float v[8];
    #pragma unroll
    for (int e = 0; e < 8; ++e) v[e] = scratch[t * 8 + e];

    casf(v[0], v[1], true);  casf(v[2], v[3], false);
    casf(v[4], v[5], true);  casf(v[6], v[7], false);
    casf(v[0], v[2], true);  casf(v[1], v[3], true);
    casf(v[4], v[6], false); casf(v[5], v[7], false);
    casf(v[0], v[1], true);  casf(v[2], v[3], true);
    casf(v[4], v[5], false); casf(v[6], v[7], false);
    sort8f(v, (ts & 1) == 0);

    #pragma unroll
    for (int kk = 16; kk <= 1024; kk <<= 1) {
        bool up = ((ts & (kk >> 3)) == 0);
        #pragma unroll
        for (int j = kk >> 1; j >= 8; j >>= 1) {
            int delta = j >> 3;
            if (delta >= 32) smem_pass(v, delta, up, t, ts, scratch);
            else             shfl_pass(v, delta, up, ts);
        }
        sort8f(v, up);
    }

    __syncthreads();
    #pragma unroll
    for (int e = 0; e < 8; ++e) scratch[t * 8 + e] = v[e];
    __syncthreads();
    // lo sorted: s[i] = scratch[i], i in [0,512]
    // hi sorted asc (-INF pads first): s[7679+j] = scratch[1024 + 511 + j]

    // ---- phase 5: lengths + first-index argmin (no decode needed) ----
    unsigned long long best = ~0ull;
    for (int i = t; i < NWIN; i += NT) {
        float len = scratch[1024 + 511 + i] - scratch[i];   // >= 0
        unsigned long long p =
            ((unsigned long long)__float_as_uint(len) << 32) | (unsigned)i;
        if (p < best) best = p;
    }
    #pragma unroll
    for (int off = 16; off; off >>= 1) {
        unsigned long long o = __shfl_down_sync(0xffffffffu, best, off);
        if (o < best) best = o;
    }
    if (lane == 0) atomicMin(&s_best, best);
    __syncthreads();

    if (t == 0) {
        int idx = (int)(unsigned)(s_best & 0xffffffffu);
        out[row]        = scratch[idx];
        out[rows + row] = scratch[1024 + 511 + idx];
    }
}

extern "C" void kernel_launch(void* const* d_in, const int* in_sizes, int n_in,
                              void* d_out, int out_size) {
    const float* x = (const float*)d_in[0];
    float* out = (float*)d_out;
    int rows = in_sizes[0] / NCOLS;   // 4096
    recall_window_kernel<<<rows, NT>>>(x, out, rows);
}

// round 10
// speedup vs baseline: 1.1912x; 1.0026x over previous
#include <cuda_runtime.h>

#define NCOLS  8192
#define NWIN   513
#define NT     256
#define KPT    32

#define TLO (-1.31f)
#define THI ( 1.31f)
#define FINF  __int_as_float(0x7f800000)
#define FNINF __int_as_float(0xff800000)

__device__ __forceinline__ unsigned f2key(float x) {
    unsigned u = __float_as_uint(x);
    return (u & 0x80000000u) ? ~u : (u | 0x80000000u);
}
__device__ __forceinline__ float key2f(unsigned k) {
    unsigned u = (k & 0x80000000u) ? (k ^ 0x80000000u) : ~k;
    return __uint_as_float(u);
}

// dual predicated FMNMX form: ptxas can emit FMNMX with predicate selecting
// min/max, avoiding the mn/mx + 2xSEL expansion.
__device__ __forceinline__ void casf(float& a, float& b, bool up) {
    float lo = up ? fminf(a, b) : fmaxf(a, b);
    float hi = up ? fmaxf(a, b) : fminf(a, b);
    a = lo; b = hi;
}

__device__ __forceinline__ void sort8f(float v[8], bool up) {
    casf(v[0], v[4], up); casf(v[1], v[5], up); casf(v[2], v[6], up); casf(v[3], v[7], up);
    casf(v[0], v[2], up); casf(v[1], v[3], up); casf(v[4], v[6], up); casf(v[5], v[7], up);
    casf(v[0], v[1], up); casf(v[2], v[3], up); casf(v[4], v[5], up); casf(v[6], v[7], up);
}

// BRANCHLESS predication (ternary, not if — R5 proof). Single predicated
// FMNMX per element: only one of min/max is ever needed.
__device__ __forceinline__ void shfl_pass(float v[8], int delta, bool up, int ts) {
    bool keepmin = (up == ((ts & delta) == 0));
    #pragma unroll
    for (int e = 0; e < 8; ++e) {
        float o = __shfl_xor_sync(0xffffffffu, v[e], delta);
        v[e] = keepmin ? fminf(v[e], o) : fmaxf(v[e], o);
    }
}

// delta >= 32: keepmin warp-uniform, branch free; 1 FMNMX per element.
__device__ __forceinline__ void smem_pass(float v[8], int delta, bool up,
                                          int t, int ts, float* scratch) {
    __syncthreads();
    #pragma unroll
    for (int e = 0; e < 8; ++e) scratch[t * 8 + e] = v[e];
    __syncthreads();
    bool keepmin = (up == ((ts & delta) == 0));
    int pt = t ^ delta;
    if (keepmin) {
        #pragma unroll
        for (int e = 0; e < 8; ++e) v[e] = fminf(v[e], scratch[pt * 8 + e]);
    } else {
        #pragma unroll
        for (int e = 0; e < 8; ++e) v[e] = fmaxf(v[e], scratch[pt * 8 + e]);
    }
}

// ---- exact fallback helpers (f2key domain; block-uniform; cold) ----
__device__ unsigned block_count(const float4* x4, unsigned K, bool ge,
                                unsigned* s_red, int tid) {
    if (tid == 0) *s_red = 0;
    __syncthreads();
    unsigned c = 0;
    for (int i = tid; i < NCOLS / 4; i += NT) {
        float4 w = x4[i];
        unsigned k0 = f2key(w.x), k1 = f2key(w.y), k2 = f2key(w.z), k3 = f2key(w.w);
        if (ge) c += (k0 >= K) + (k1 >= K) + (k2 >= K) + (k3 >= K);
        else    c += (k0 <= K) + (k1 <= K) + (k2 <= K) + (k3 <= K);
    }
    #pragma unroll
    for (int off = 16; off; off >>= 1) c += __shfl_down_sync(0xffffffffu, c, off);
    if ((tid & 31) == 0) atomicAdd(s_red, c);
    __syncthreads();
    unsigned r = *s_red;
    __syncthreads();
    return r;
}

// gathers as FLOATS (key2f applied); side 0: key<T, side 1: key>T
__device__ unsigned gather_side(const float4* x4, unsigned T, int side,
                                float* seg, unsigned* s_c, int tid) {
    if (tid == 0) *s_c = 0;
    __syncthreads();
    const int lane = tid & 31;
    for (int i = tid; i < NCOLS / 4; i += NT) {
        float4 w = x4[i];
        unsigned kk[4] = { f2key(w.x), f2key(w.y), f2key(w.z), f2key(w.w) };
        #pragma unroll
        for (int q = 0; q < 4; ++q) {
            bool take = side ? (kk[q] > T) : (kk[q] < T);
            unsigned m = __ballot_sync(0xffffffffu, take);
            unsigned base = 0;
            if (lane == 0 && m) base = atomicAdd(s_c, (unsigned)__popc(m));
            base = __shfl_sync(0xffffffffu, base, 0);
            if (take) {
                unsigned p = base + __popc(m & ((1u << lane) - 1u));
                if (p < 1024) seg[p] = key2f(kk[q]);
            }
        }
    }
    __syncthreads();
    unsigned r = *s_c;
    __syncthreads();
    return r;
}

__global__ __launch_bounds__(NT, 6)
void recall_window_kernel(const float* __restrict__ x,
                          float* __restrict__ out, int rows)
{
    __shared__ float    scratch[2048];     // two 1024-float sort segments
    __shared__ unsigned wsum[8];
    __shared__ unsigned s_c;
    __shared__ unsigned long long s_best;

    const int t    = threadIdx.x;
    const int lane = t & 31;
    const int wid  = t >> 5;
    const int ts   = t & 127;
    const int row  = blockIdx.x;
    const float4* x4 = reinterpret_cast<const float4*>(x + (size_t)row * NCOLS);

    // ---- phase 1: load + count tail takes ----
    unsigned clo = 0, chi = 0;
    #pragma unroll
    for (int e4 = 0; e4 < KPT / 4; ++e4) {
        float4 w = x4[e4 * NT + t];
        clo += (w.x < TLO) + (w.y < TLO) + (w.z < TLO) + (w.w < TLO);
        chi += (w.x > THI) + (w.y > THI) + (w.z > THI) + (w.w > THI);
    }

    // ---- phase 2: block exclusive scan of packed (clo | chi<<16) ----
    unsigned packed = clo | (chi << 16);
    unsigned incl = packed;
    #pragma unroll
    for (int off = 1; off < 32; off <<= 1) {
        unsigned v = __shfl_up_sync(0xffffffffu, incl, off);
        if (lane >= off) incl += v;
    }
    if (lane == 31) wsum[wid] = incl;
    __syncthreads();
    unsigned wbase = 0, tot = 0;
    #pragma unroll
    for (int w = 0; w < 8; ++w) {
        unsigned s = wsum[w];
        if (w < wid) wbase += s;
        tot += s;
    }
    unsigned excl   = wbase + incl - packed;
    unsigned baselo = excl & 0xFFFFu, basehi = excl >> 16;
    unsigned totlo  = tot  & 0xFFFFu, tothi  = tot  >> 16;

    const bool ok_lo = (totlo >= 513u && totlo <= 1024u);
    const bool ok_hi = (tothi >= 513u && tothi <= 1024u);

    // ---- phase 3: re-read row (cache-hot), scatter floats directly ----
    if (ok_lo && ok_hi) {
        unsigned plo = baselo, phi = basehi;
        #pragma unroll
        for (int e4 = 0; e4 < KPT / 4; ++e4) {
            float4 w = x4[e4 * NT + t];
            float fa[4] = { w.x, w.y, w.z, w.w };
            #pragma unroll
            for (int q = 0; q < 4; ++q) {
                float f = fa[q];
                if (f < TLO)      scratch[plo++] = f;
                else if (f > THI) scratch[1024 + phi++] = f;
            }
        }
    }
    __syncthreads();

    unsigned c0 = totlo, c1 = tothi;
    if (!ok_lo) {                                   // exact fallback (cold)
        unsigned Kcut;
        if (block_count(x4, 0u, false, &s_c, t) >= 513u) {
            Kcut = 0u;
        } else {
            unsigned X = 0;
            for (int b = 31; b >= 0; --b) {
                unsigned X2 = X | (1u << b);
                if (block_count(x4, X2, false, &s_c, t) < 513u) X = X2;
            }
            Kcut = X + 1u;                          // exact s[512] key
        }
        c0 = gather_side(x4, Kcut, 0, scratch, &s_c, t);
        float fK = key2f(Kcut);
        for (int i = (int)c0 + t; i < 513; i += NT) scratch[i] = fK;
        c0 = 513u;
    }
    if (!ok_hi) {
        unsigned Y = 0;
        for (int b = 31; b >= 0; --b) {
            unsigned Y2 = Y | (1u << b);
            if (block_count(x4, Y2, true, &s_c, t) >= 513u) Y = Y2;   // exact s[7679]
        }
        c1 = gather_side(x4, Y, 1, scratch + 1024, &s_c, t);
        float fY = key2f(Y);
        for (int i = (int)c1 + t; i < 513; i += NT) scratch[1024 + i] = fY;
        c1 = 513u;
    }
    // pads: lo-end with +INF, hi-front with -INF
    for (int i = (int)c0 + t; i < 1024; i += NT) scratch[i]        = FINF;
    for (int i = (int)c1 + t; i < 1024; i += NT) scratch[1024 + i] = FNINF;
    if (t == 0) s_best = ~0ull;
    __syncthreads();

    // ---- phase 4: register-blocked float bitonic, two independent 1024 sorts ----
    float v[8];
    #pragma unroll
    for (int e = 0; e < 8; ++e) v[e] = scratch[t * 8 + e];

    casf(v[0], v[1], true);  casf(v[2], v[3], false);
    casf(v[4], v[5], true);  casf(v[6], v[7], false);
    casf(v[0], v[2], true);  casf(v[1], v[3], true);
    casf(v[4], v[6], false); casf(v[5], v[7], false);
    casf(v[0], v[1], true);  casf(v[2], v[3], true);
    casf(v[4], v[5], false); casf(v[6], v[7], false);
    sort8f(v, (ts & 1) == 0);

    #pragma unroll
    for (int kk = 16; kk <= 1024; kk <<= 1) {
        bool up = ((ts & (kk >> 3)) == 0);
        #pragma unroll
        for (int j = kk >> 1; j >= 8; j >>= 1) {
            int delta = j >> 3;
            if (delta >= 32) smem_pass(v, delta, up, t, ts, scratch);
            else             shfl_pass(v, delta, up, ts);
        }
        sort8f(v, up);
    }

    __syncthreads();
    #pragma unroll
    for (int e = 0; e < 8; ++e) scratch[t * 8 + e] = v[e];
    __syncthreads();
    // lo sorted: s[i] = scratch[i], i in [0,512]
    // hi sorted asc (-INF pads first): s[7679+j] = scratch[1024 + 511 + j]

    // ---- phase 5: lengths + first-index argmin ----
    unsigned long long best = ~0ull;
    for (int i = t; i < NWIN; i += NT) {
        float len = scratch[1024 + 511 + i] - scratch[i];   // >= 0
        unsigned long long p =
            ((unsigned long long)__float_as_uint(len) << 32) | (unsigned)i;
        if (p < best) best = p;
    }
    #pragma unroll
    for (int off = 16; off; off >>= 1) {
        unsigned long long o = __shfl_down_sync(0xffffffffu, best, off);
        if (o < best) best = o;
    }
    if (lane == 0) atomicMin(&s_best, best);
    __syncthreads();

    if (t == 0) {
        int idx = (int)(unsigned)(s_best & 0xffffffffu);
        out[row]        = scratch[idx];
        out[rows + row] = scratch[1024 + 511 + idx];
    }
}

extern "C" void kernel_launch(void* const* d_in, const int* in_sizes, int n_in,
                              void* d_out, int out_size) {
    const float* x = (const float*)d_in[0];
    float* out = (float*)d_out;
    int rows = in_sizes[0] / NCOLS;   // 4096
    recall_window_kernel<<<rows, NT>>>(x, out, rows);
}